// round 14
// baseline (speedup 1.0000x reference)
#include <cuda_runtime.h>

// Problem constants (fixed shapes for this problem instance)
#define NBOX   2048
#define NBATCH 16
#define AH     256
#define AW     256
#define GRID   1024  // 16 batches x 64 bands (4 rows per block)

__device__ float    g_partial[GRID];
__device__ unsigned g_count = 0;

// bce = max(l,0) - l*m + log1p(exp(-|l|)); softplus arg in (1,2] -> fast math safe
__device__ __forceinline__ float bce_elem(float l, unsigned mb) {
    float t  = __expf(-fabsf(l));
    float sp = __logf(1.0f + t);
    float z  = fmaxf(l, 0.0f) - (mb ? l : 0.0f);
    return z + sp;
}

// Release-ordered counter bump: orders this block's prior partial store at L2
// without a gpu-scope membar / L1 flush.
__device__ __forceinline__ unsigned atom_inc_release(unsigned* p) {
    unsigned prev;
    asm volatile("atom.add.release.gpu.global.u32 %0, [%1], 1;"
                 : "=r"(prev) : "l"(p) : "memory");
    return prev;
}

__global__ __launch_bounds__(256, 8)
void la_loss_kernel(const float* __restrict__ am,
                    const float* __restrict__ tgt,
                    float* __restrict__ out)
{
    const int tid   = threadIdx.x;
    const int blk   = blockIdx.x;
    const int batch = blk >> 6;        // 0..15
    const int band  = blk & 63;        // 0..63
    const int blo   = band << 2;       // first row of 4-row band

    // ---- Front-batched loads, CRITICAL-PATH-FIRST issue order:
    // sample (needed at first barrier) BEFORE logits (needed much later).
    const float  sv = tgt[(size_t)tid * 48];                      // bidx[8*tid]
    const float4 v  = ((const float4*)am)[(size_t)blk * 256 + tid];

    __shared__ unsigned s_mask[4 * 8];     // 4 rows x 256 bits
    __shared__ int      s_cnt1[8];         // per-warp counts of (sv < b+1)
    __shared__ float    s_warp[8];
    __shared__ unsigned s_last;

    if (tid < 32) s_mask[tid] = 0u;

    // ---- Phase 0: sampled range-find on sorted bidx, ONE barrier ----
    // j0 = #samples < b (via syncthreads_count), j1 = #samples < b+1 (via
    // per-warp ballots stored pre-barrier). All batch-b boxes lie in
    // [max(0, 8*j0-7), min(NBOX, 8*j1+1)).
    const float fb  = (float)batch;
    const float fb1 = (float)(batch + 1);
    {
        unsigned b1 = __ballot_sync(0xFFFFFFFFu, sv < fb1);
        if ((tid & 31) == 0) s_cnt1[tid >> 5] = __popc(b1);   // plain store, own slot
    }
    const int j0 = __syncthreads_count(sv < fb);   // also publishes s_cnt1 + s_mask
    int j1 = 0;
    #pragma unroll
    for (int w = 0; w < 8; w++) j1 += s_cnt1[w];
    const int lo = max(0, (j0 << 3) - 7);
    const int hi = min(NBOX, (j1 << 3) + 1);

    // ---- Phase 1: scan bracketed window; all box fields loaded in ONE trip ----
    int has = 0;
    for (int i = lo + tid; i < hi; i += 256) {
        const float2* t6 = (const float2*)(tgt + (size_t)i * 6);  // 8B-aligned
        float2 a01 = t6[0];   // bidx, cls
        float2 a23 = t6[1];   // xc, yc
        float2 a45 = t6[2];   // bw, bh      (3 LDG.64 issued together, MLP=3)
        if (a01.x == fb) {
            has = 1;
            float x1 = 1024.0f * (a23.x - a45.x * 0.5f);
            float y1 = 1024.0f * (a23.y - a45.y * 0.5f);
            float x2 = 1024.0f * (a23.x + a45.x * 0.5f);
            float y2 = 1024.0f * (a23.y + a45.y * 0.5f);
            bool valid = (x1 <= 1024.0f) && (y1 <= 1024.0f) &&
                         (x2 <= 1024.0f) && (y2 <= 1024.0f);
            int X1 = max(0, (int)truncf(x1 * 0.25f));
            int Y1 = max(0, (int)truncf(y1 * 0.25f));
            int X2 = max(0, min(AW, (int)(ceilf(x2 * 0.25f) + 1.0f)));
            int Y2 = max(0, min(AH, (int)(ceilf(y2 * 0.25f) + 1.0f)));
            int y0  = max(Y1, blo);
            int y1i = min(Y2, blo + 4);
            if (valid && X2 > X1 && y0 < y1i) {
                int w0 = X1 >> 5;
                int w1 = (X2 - 1) >> 5;
                for (int w = w0; w <= w1; w++) {
                    int lob = X1 - (w << 5); lob = (lob < 0) ? 0 : lob;  // 0..31
                    int hib = X2 - (w << 5);                             // >=1
                    unsigned mh  = (hib >= 32) ? 0xFFFFFFFFu : ((1u << hib) - 1u);
                    unsigned msk = mh & ~((1u << lob) - 1u);
                    for (int y = y0; y < y1i; y++)
                        atomicOr(&s_mask[((y - blo) << 3) + w], msk);
                }
            }
        }
    }
    const int anyhas = __syncthreads_or(has);   // barrier + block-wide has_box

    // ---- Phase 2: BCE over prefetched logits (4 elems/thread) ----
    float sum;
    {
        int ty  = tid >> 6;                  // row in band (0..3)
        int col = (tid & 63) << 2;           // starting bit
        unsigned bits = s_mask[(ty << 3) + (col >> 5)] >> (col & 31);
        sum  = bce_elem(v.x,  bits       & 1u);
        sum += bce_elem(v.y, (bits >> 1) & 1u);
        sum += bce_elem(v.z, (bits >> 2) & 1u);
        sum += bce_elem(v.w, (bits >> 3) & 1u);
    }

    // ---- Phase 3: block reduce (fixed order), publish partial ----
    #pragma unroll
    for (int off = 16; off; off >>= 1)
        sum += __shfl_down_sync(0xFFFFFFFFu, sum, off);
    if ((tid & 31) == 0) s_warp[tid >> 5] = sum;
    __syncthreads();
    if (tid == 0) {
        float tot = 0.0f;
        #pragma unroll
        for (int w = 0; w < 8; w++) tot += s_warp[w];          // fixed order
        g_partial[blk] = anyhas ? tot * (1.0f / 65536.0f) : 0.0f;
        unsigned prev = atom_inc_release(&g_count);
        s_last = (prev == (unsigned)(gridDim.x - 1)) ? 1u : 0u;
    }
    __syncthreads();

    // ---- Phase 4: last block sums all partials in fixed order ----
    if (s_last) {
        __threadfence();   // single acquire-side fence, one block only
        volatile float* gp = g_partial;
        float t0 = (gp[tid]       + gp[tid + 256]) +
                   (gp[tid + 512] + gp[tid + 768]);
        #pragma unroll
        for (int off = 16; off; off >>= 1)
            t0 += __shfl_down_sync(0xFFFFFFFFu, t0, off);
        if ((tid & 31) == 0) s_warp[tid >> 5] = t0;
        __syncthreads();
        if (tid == 0) {
            float tot = 0.0f;
            #pragma unroll
            for (int w = 0; w < 8; w++) tot += s_warp[w];      // fixed order
            out[0]  = tot;
            g_count = 0u;   // reset for next graph replay
        }
    }
}

extern "C" void kernel_launch(void* const* d_in, const int* in_sizes, int n_in,
                              void* d_out, int out_size)
{
    const float* am  = (const float*)d_in[0];  // attention_mask (16,1,256,256) f32
    const float* tgt = (const float*)d_in[1];  // target (2048,6) f32
    (void)in_sizes; (void)n_in; (void)out_size;
    la_loss_kernel<<<GRID, 256>>>(am, tgt, (float*)d_out);
}

// round 15
// speedup vs baseline: 1.2308x; 1.2308x over previous
#include <cuda_runtime.h>

// Problem constants (fixed shapes for this problem instance)
#define NBOX   2048
#define NBATCH 16
#define AH     256
#define AW     256
#define GRID   1024  // 16 batches x 64 bands (4 rows per block)

__device__ float    g_partial[GRID];
__device__ unsigned g_count = 0;

// bce = max(l,0) - l*m + log1p(exp(-|l|)); softplus arg in (1,2] -> fast math safe
__device__ __forceinline__ float bce_elem(float l, unsigned mb) {
    float t  = __expf(-fabsf(l));
    float sp = __logf(1.0f + t);
    float z  = fmaxf(l, 0.0f) - (mb ? l : 0.0f);
    return z + sp;
}

// Release-ordered counter bump: orders this block's prior partial store at L2
// without a gpu-scope membar / L1 flush.
__device__ __forceinline__ unsigned atom_inc_release(unsigned* p) {
    unsigned prev;
    asm volatile("atom.add.release.gpu.global.u32 %0, [%1], 1;"
                 : "=r"(prev) : "l"(p) : "memory");
    return prev;
}

// Streaming (evict-first) float4 load: don't let the 4MB logit stream evict
// the L1-resident target data that every block re-reads.
__device__ __forceinline__ float4 ldcs_f4(const float4* p) {
    float4 r;
    asm volatile("ld.global.cs.v4.f32 {%0,%1,%2,%3}, [%4];"
                 : "=f"(r.x), "=f"(r.y), "=f"(r.z), "=f"(r.w) : "l"(p));
    return r;
}

__global__ __launch_bounds__(256, 8)
void la_loss_kernel(const float* __restrict__ am,
                    const float* __restrict__ tgt,
                    float* __restrict__ out)
{
    const int tid   = threadIdx.x;
    const int blk   = blockIdx.x;
    const int batch = blk >> 6;        // 0..15
    const int band  = blk & 63;        // 0..63
    const int blo   = band << 2;       // first row of 4-row band

    // ---- Front-batched loads, critical-path-first issue order.
    // 128 samples at stride 16 (threads >=128 contribute +inf): halves the
    // uncoalesced-gather wavefront cost vs 256 samples at stride 8.
    const float  sv = (tid < 128) ? tgt[(size_t)tid * 96] : 1.0e9f;  // bidx[16*tid]
    const float4 v  = ldcs_f4(((const float4*)am) + (size_t)blk * 256 + tid);

    __shared__ unsigned s_mask[4 * 8];     // 4 rows x 256 bits
    __shared__ int      s_cnt1[8];         // per-warp counts of (sv < b+1)
    __shared__ float    s_warp[8];
    __shared__ unsigned s_last;

    if (tid < 32) s_mask[tid] = 0u;

    // ---- Phase 0: sampled range-find on sorted bidx, ONE barrier ----
    // j0 = #samples < b, j1 = #samples < b+1 (128 samples, stride 16)
    // => all batch-b boxes lie in [max(0,16*j0-15), min(NBOX,16*j1+1)).
    const float fb  = (float)batch;
    const float fb1 = (float)(batch + 1);
    {
        unsigned b1 = __ballot_sync(0xFFFFFFFFu, sv < fb1);
        if ((tid & 31) == 0) s_cnt1[tid >> 5] = __popc(b1);   // plain store, own slot
    }
    const int j0 = __syncthreads_count(sv < fb);   // also publishes s_cnt1 + s_mask
    int j1 = 0;
    #pragma unroll
    for (int w = 0; w < 8; w++) j1 += s_cnt1[w];
    const int lo = max(0, (j0 << 4) - 15);
    const int hi = min(NBOX, (j1 << 4) + 1);

    // ---- Phase 1: scan bracketed window; all box fields loaded in ONE trip ----
    int has = 0;
    for (int i = lo + tid; i < hi; i += 256) {
        const float2* t6 = (const float2*)(tgt + (size_t)i * 6);  // 8B-aligned
        float2 a01 = t6[0];   // bidx, cls
        float2 a23 = t6[1];   // xc, yc
        float2 a45 = t6[2];   // bw, bh      (3 LDG.64 issued together, MLP=3)
        if (a01.x == fb) {
            has = 1;
            float x1 = 1024.0f * (a23.x - a45.x * 0.5f);
            float y1 = 1024.0f * (a23.y - a45.y * 0.5f);
            float x2 = 1024.0f * (a23.x + a45.x * 0.5f);
            float y2 = 1024.0f * (a23.y + a45.y * 0.5f);
            bool valid = (x1 <= 1024.0f) && (y1 <= 1024.0f) &&
                         (x2 <= 1024.0f) && (y2 <= 1024.0f);
            int X1 = max(0, (int)truncf(x1 * 0.25f));
            int Y1 = max(0, (int)truncf(y1 * 0.25f));
            int X2 = max(0, min(AW, (int)(ceilf(x2 * 0.25f) + 1.0f)));
            int Y2 = max(0, min(AH, (int)(ceilf(y2 * 0.25f) + 1.0f)));
            int y0  = max(Y1, blo);
            int y1i = min(Y2, blo + 4);
            if (valid && X2 > X1 && y0 < y1i) {
                int w0 = X1 >> 5;
                int w1 = (X2 - 1) >> 5;
                for (int w = w0; w <= w1; w++) {
                    int lob = X1 - (w << 5); lob = (lob < 0) ? 0 : lob;  // 0..31
                    int hib = X2 - (w << 5);                             // >=1
                    unsigned mh  = (hib >= 32) ? 0xFFFFFFFFu : ((1u << hib) - 1u);
                    unsigned msk = mh & ~((1u << lob) - 1u);
                    for (int y = y0; y < y1i; y++)
                        atomicOr(&s_mask[((y - blo) << 3) + w], msk);
                }
            }
        }
    }
    const int anyhas = __syncthreads_or(has);   // barrier + block-wide has_box

    // ---- Phase 2: BCE over prefetched logits (4 elems/thread) ----
    float sum;
    {
        int ty  = tid >> 6;                  // row in band (0..3)
        int col = (tid & 63) << 2;           // starting bit
        unsigned bits = s_mask[(ty << 3) + (col >> 5)] >> (col & 31);
        sum  = bce_elem(v.x,  bits       & 1u);
        sum += bce_elem(v.y, (bits >> 1) & 1u);
        sum += bce_elem(v.z, (bits >> 2) & 1u);
        sum += bce_elem(v.w, (bits >> 3) & 1u);
    }

    // ---- Phase 3: block reduce (fixed order), publish partial ----
    #pragma unroll
    for (int off = 16; off; off >>= 1)
        sum += __shfl_down_sync(0xFFFFFFFFu, sum, off);
    if ((tid & 31) == 0) s_warp[tid >> 5] = sum;
    __syncthreads();
    if (tid == 0) {
        float tot = 0.0f;
        #pragma unroll
        for (int w = 0; w < 8; w++) tot += s_warp[w];          // fixed order
        g_partial[blk] = anyhas ? tot * (1.0f / 65536.0f) : 0.0f;
        unsigned prev = atom_inc_release(&g_count);
        s_last = (prev == (unsigned)(gridDim.x - 1)) ? 1u : 0u;
    }
    __syncthreads();

    // ---- Phase 4: last block sums all partials in fixed order ----
    if (s_last) {
        __threadfence();   // single acquire-side fence, one block only
        volatile float* gp = g_partial;
        float t0 = (gp[tid]       + gp[tid + 256]) +
                   (gp[tid + 512] + gp[tid + 768]);
        #pragma unroll
        for (int off = 16; off; off >>= 1)
            t0 += __shfl_down_sync(0xFFFFFFFFu, t0, off);
        if ((tid & 31) == 0) s_warp[tid >> 5] = t0;
        __syncthreads();
        if (tid == 0) {
            float tot = 0.0f;
            #pragma unroll
            for (int w = 0; w < 8; w++) tot += s_warp[w];      // fixed order
            out[0]  = tot;
            g_count = 0u;   // reset for next graph replay
        }
    }
}

extern "C" void kernel_launch(void* const* d_in, const int* in_sizes, int n_in,
                              void* d_out, int out_size)
{
    const float* am  = (const float*)d_in[0];  // attention_mask (16,1,256,256) f32
    const float* tgt = (const float*)d_in[1];  // target (2048,6) f32
    (void)in_sizes; (void)n_in; (void)out_size;
    la_loss_kernel<<<GRID, 256>>>(am, tgt, (float*)d_out);
}